// round 11
// baseline (speedup 1.0000x reference)
#include <cuda_runtime.h>
#include <math.h>
#include <stdint.h>

#define TWO_PI 6.28318530717958647692f

// Scratch
// g_Bf[h][j(5)][kt(8)][ntp(8)][gid(8)][tg(4)][q(4)]:
//   q: 0 -> B_j[o=(2ntp)*8+gid][c=kt*8+tg]
//      1 -> B_j[same o][c=kt*8+tg+4]
//      2 -> B_j[o=(2ntp+1)*8+gid][c=kt*8+tg]
//      3 -> B_j[same o][c=kt*8+tg+4]
__device__ float g_Bf[128 * 40960];
__device__ float g_stats[512];        // [(part*128+o)*2 + {sum,sq}]
__device__ float g_bnp[512];          // [(part*128+o)*2 + {scale,shift}]

__device__ __forceinline__ uint32_t f2tf(float x) {
    uint32_t u;
    asm("cvt.rna.tf32.f32 %0, %1;" : "=r"(u) : "f"(x));
    return u;
}
__device__ __forceinline__ void mma_tf32(float* d, const uint32_t* a,
                                         const uint32_t* b) {
    asm volatile(
        "mma.sync.aligned.m16n8k8.row.col.f32.tf32.tf32.f32 "
        "{%0,%1,%2,%3}, {%4,%5,%6,%7}, {%8,%9}, {%0,%1,%2,%3};"
        : "+f"(d[0]), "+f"(d[1]), "+f"(d[2]), "+f"(d[3])
        : "r"(a[0]), "r"(a[1]), "r"(a[2]), "r"(a[3]), "r"(b[0]), "r"(b[1]));
}

// ---------------------------------------------------------------------------
__global__ void zero_stats_kernel() {
    if (threadIdx.x < 512) g_stats[threadIdx.x] = 0.f;
}

// B_j[o][c], j in {P0, P1, -Q1, P2, -Q2}, fragment-pair layout (see above).
__global__ void precompute_B_kernel(const float* __restrict__ filters) {
    __shared__ float ct[128], st[128];
    int h = blockIdx.x, t = threadIdx.x;
    if (t < 128) {
        float s_, c_;
        sincosf(TWO_PI * (float)t * (1.f / 128.f), &s_, &c_);
        ct[t] = c_; st[t] = s_;
    }
    __syncthreads();
    for (int e = t; e < 40960; e += blockDim.x) {
        int q   = e & 3;
        int tg  = (e >> 2) & 3;
        int gid = (e >> 4) & 7;
        int ntp = (e >> 7) & 7;
        int kt  = (e >> 10) & 7;
        int j   = e >> 13;
        int nt  = 2 * ntp + (q >> 1);
        int c   = kt * 8 + tg + (q & 1) * 4;
        int o   = nt * 8 + gid;
        int v = (j + 1) >> 1;                       // {0,1,1,2,2}
        bool sn = (j > 0) && ((j & 1) == 0);        // j==2 || j==4 -> -Q
        float acc = 0.f;
        #pragma unroll
        for (int u = 0; u < 3; u++) {
            int a = (h * u) & 127;
            float tr = sn ? st[a] : ct[a];
            acc = fmaf(tr, filters[(u * 3 + v) * 8192 + c * 128 + o], acc);
        }
        g_Bf[h * 40960 + e] = sn ? -acc : acc;
    }
}

// ---------------------------------------------------------------------------
// Conv: 128 CTAs (one per h), 256 threads (8 warps), no main-loop barriers.
// Warp = one w per iteration (16 iterations). Per (j,kt) step: 8 batched
// conflict-free lds.128 (B fragment pairs), then 16 mma. A fragments come
// from gmem, w-coefficients folded into A. Accumulators + BN stats in regs.
#define SMEM_CONV (163840 + 2048)

__global__ __launch_bounds__(256, 1) void conv_mma_kernel(
    const float* __restrict__ xr, const float* __restrict__ xi,
    float* __restrict__ out)
{
    extern __shared__ float smem[];
    float* Bs = smem;                    // 40960 floats = 160KB
    float* red = smem + 40960;           // 512 floats

    const int h = blockIdx.x, t = threadIdx.x;
    const int lane = t & 31, wid = t >> 5;
    const int gid = lane >> 2, tg = lane & 3;
    const int n0 = gid >> 1, part = gid & 1;

    // load resident B (coalesced float4, layout-agnostic copy)
    {
        const float4* src = (const float4*)(g_Bf + h * 40960);
        float4* dst = (float4*)Bs;
        for (int g = t; g < 10240; g += 256) dst[g] = src[g];
    }
    for (int i = t; i < 512; i += 256) red[i] = 0.f;
    __syncthreads();

    // persistent BN stat registers: per nt, o-pair (2tg, 2tg+1)
    float ss0[16], qq0[16], ss1[16], qq1[16];
    #pragma unroll
    for (int i = 0; i < 16; i++) { ss0[i] = 0.f; qq0[i] = 0.f; ss1[i] = 0.f; qq1[i] = 0.f; }

    const float* xr0 = xr + ((size_t)(n0 * 128 + h) * 128) * 64;
    const float* xi0 = xi + ((size_t)(n0 * 128 + h) * 128) * 64;
    const float* xr4 = xr + ((size_t)((n0 + 4) * 128 + h) * 128) * 64;
    const float* xi4 = xi + ((size_t)((n0 + 4) * 128 + h) * 128) * 64;

    const float4* B4 = (const float4*)Bs;

    for (int it = 0; it < 16; it++) {
        const int w = it * 8 + wid;
        const float* pr0 = xr0 + w * 64;
        const float* pi0 = xi0 + w * 64;
        const float* pr4 = xr4 + w * 64;
        const float* pi4 = xi4 + w * 64;

        // raw A fragments (S or D by part), all 8 k-tiles
        float rawA[32];
        #pragma unroll
        for (int kt = 0; kt < 8; kt++) {
            int c0 = kt * 8 + tg, c1 = c0 + 4;
            float r0 = pr0[c0], i0 = pi0[c0];
            float r4 = pr4[c0], i4 = pi4[c0];
            float r0b = pr0[c1], i0b = pi0[c1];
            float r4b = pr4[c1], i4b = pi4[c1];
            rawA[kt * 4 + 0] = part ? (i0 - r0) : (r0 + i0);
            rawA[kt * 4 + 1] = part ? (i4 - r4) : (r4 + i4);
            rawA[kt * 4 + 2] = part ? (i0b - r0b) : (r0b + i0b);
            rawA[kt * 4 + 3] = part ? (i4b - r4b) : (r4b + i4b);
        }

        float s1, c1f, s2, c2f;
        sincosf(TWO_PI * (float)w * (1.f / 128.f), &s1, &c1f);
        sincosf(TWO_PI * (float)((2 * w) & 127) * (1.f / 128.f), &s2, &c2f);

        float acc[16][4];
        #pragma unroll
        for (int nt = 0; nt < 16; nt++) {
            acc[nt][0] = 0.f; acc[nt][1] = 0.f; acc[nt][2] = 0.f; acc[nt][3] = 0.f;
        }

        #pragma unroll
        for (int s = 0; s < 40; s++) {
            const int j = s >> 3, kt = s & 7;
            const float cf = (j == 0) ? 1.f
                            : (j == 1) ? c1f
                            : (j == 2) ? s1
                            : (j == 3) ? c2f : s2;
            // batched conflict-free lds.128: 8 fragment-pairs for this step
            float4 cur[8];
            #pragma unroll
            for (int p = 0; p < 8; p++)
                cur[p] = B4[s * 256 + p * 32 + lane];
            uint32_t a[4];
            a[0] = f2tf(cf * rawA[kt * 4 + 0]);
            a[1] = f2tf(cf * rawA[kt * 4 + 1]);
            a[2] = f2tf(cf * rawA[kt * 4 + 2]);
            a[3] = f2tf(cf * rawA[kt * 4 + 3]);
            #pragma unroll
            for (int p = 0; p < 8; p++) {
                mma_tf32(acc[2 * p],     a, (const uint32_t*)&cur[p].x);
                mma_tf32(acc[2 * p + 1], a, (const uint32_t*)&cur[p].z);
            }
        }

        // epilogue: store raw conv outputs + accumulate BN stats
        size_t ob = (size_t)part * 16777216 +
                    (((size_t)(n0 * 128 + h)) * 128 + w) * 128;
        size_t ob4 = ob + (size_t)4 * 128 * 128 * 128;
        #pragma unroll
        for (int nt = 0; nt < 16; nt++) {
            int o = nt * 8 + 2 * tg;
            *(float2*)(out + ob + o)  = make_float2(acc[nt][0], acc[nt][1]);
            *(float2*)(out + ob4 + o) = make_float2(acc[nt][2], acc[nt][3]);
            ss0[nt] += acc[nt][0] + acc[nt][2];
            qq0[nt] = fmaf(acc[nt][0], acc[nt][0], qq0[nt]);
            qq0[nt] = fmaf(acc[nt][2], acc[nt][2], qq0[nt]);
            ss1[nt] += acc[nt][1] + acc[nt][3];
            qq1[nt] = fmaf(acc[nt][1], acc[nt][1], qq1[nt]);
            qq1[nt] = fmaf(acc[nt][3], acc[nt][3], qq1[nt]);
        }
    }

    // stats: shuffle-reduce over same-part lanes (lane^8, lane^16), then smem
    #pragma unroll
    for (int nt = 0; nt < 16; nt++) {
        ss0[nt] += __shfl_xor_sync(~0u, ss0[nt], 8);
        ss0[nt] += __shfl_xor_sync(~0u, ss0[nt], 16);
        qq0[nt] += __shfl_xor_sync(~0u, qq0[nt], 8);
        qq0[nt] += __shfl_xor_sync(~0u, qq0[nt], 16);
        ss1[nt] += __shfl_xor_sync(~0u, ss1[nt], 8);
        ss1[nt] += __shfl_xor_sync(~0u, ss1[nt], 16);
        qq1[nt] += __shfl_xor_sync(~0u, qq1[nt], 8);
        qq1[nt] += __shfl_xor_sync(~0u, qq1[nt], 16);
    }
    if (lane < 8) {   // gid in {0,1}: part = gid, tg = lane&3
        #pragma unroll
        for (int nt = 0; nt < 16; nt++) {
            int o = nt * 8 + 2 * tg;
            atomicAdd(&red[(part * 128 + o) * 2 + 0], ss0[nt]);
            atomicAdd(&red[(part * 128 + o) * 2 + 1], qq0[nt]);
            atomicAdd(&red[(part * 128 + o + 1) * 2 + 0], ss1[nt]);
            atomicAdd(&red[(part * 128 + o + 1) * 2 + 1], qq1[nt]);
        }
    }
    __syncthreads();
    for (int i = t; i < 512; i += 256) atomicAdd(&g_stats[i], red[i]);
}

// ---------------------------------------------------------------------------
__global__ void bn_finalize_kernel(const float* __restrict__ gr,
                                   const float* __restrict__ br,
                                   const float* __restrict__ gi,
                                   const float* __restrict__ bi) {
    int t = threadIdx.x, part = t >> 7, o = t & 127;
    float sum = g_stats[t * 2 + 0], ss = g_stats[t * 2 + 1];
    const float inv = 1.f / 131072.f;
    float mean = sum * inv;
    float var = fmaf(-mean, mean, ss * inv);
    float gamma = part ? gi[o] : gr[o];
    float beta = part ? bi[o] : br[o];
    float a = gamma * rsqrtf(var + 1e-3f);
    g_bnp[t * 2 + 0] = a;
    g_bnp[t * 2 + 1] = fmaf(-mean, a, beta);
}

__global__ void bn_apply_kernel(float* __restrict__ out) {
    __shared__ float bp[512];
    int t = threadIdx.x;
    bp[t] = g_bnp[t];
    bp[t + 256] = g_bnp[t + 256];
    __syncthreads();
    const int total4 = 33554432 / 4;
    float4* o4 = (float4*)out;
    for (int i = blockIdx.x * blockDim.x + t; i < total4;
         i += gridDim.x * blockDim.x) {
        float4 x = o4[i];
        int e0 = i << 2;
        const float* b = bp + (e0 >> 24) * 256 + (e0 & 127) * 2;
        float v;
        v = fmaf(b[0], x.x, b[1]); x.x = v >= 0.f ? v : 0.2f * v;
        v = fmaf(b[2], x.y, b[3]); x.y = v >= 0.f ? v : 0.2f * v;
        v = fmaf(b[4], x.z, b[5]); x.z = v >= 0.f ? v : 0.2f * v;
        v = fmaf(b[6], x.w, b[7]); x.w = v >= 0.f ? v : 0.2f * v;
        o4[i] = x;
    }
}

// ---------------------------------------------------------------------------
extern "C" void kernel_launch(void* const* d_in, const int* in_sizes, int n_in,
                              void* d_out, int out_size) {
    const float* xr = (const float*)d_in[0];
    const float* xi = (const float*)d_in[1];
    const float* f  = (const float*)d_in[2];
    const float* gr = (const float*)d_in[3];
    const float* br = (const float*)d_in[4];
    const float* gi = (const float*)d_in[5];
    const float* bi = (const float*)d_in[6];
    float* out = (float*)d_out;

    cudaFuncSetAttribute(conv_mma_kernel,
                         cudaFuncAttributeMaxDynamicSharedMemorySize, SMEM_CONV);

    zero_stats_kernel<<<1, 512>>>();
    precompute_B_kernel<<<128, 256>>>(f);
    conv_mma_kernel<<<128, 256, SMEM_CONV>>>(xr, xi, out);
    bn_finalize_kernel<<<1, 256>>>(gr, br, gi, bi);
    bn_apply_kernel<<<2048, 256>>>(out);
}

// round 12
// speedup vs baseline: 1.3552x; 1.3552x over previous
#include <cuda_runtime.h>
#include <cuda_fp16.h>
#include <math.h>
#include <stdint.h>

#define TWO_PI 6.28318530717958647692f

// Scratch
// g_Bh[h][j(5)][kt(4)][ntp(8)][gid(8)][tg(4)][q(4)] : uint32 = half2
//   q=0: (B[o=2ntp*8+gid][c], B[..][c+1])      c = kt*16 + 2tg        (b0, nt=2ntp)
//   q=1: same o, c+8,c+9                                              (b1, nt=2ntp)
//   q=2: o=(2ntp+1)*8+gid, c,c+1                                      (b0, nt=2ntp+1)
//   q=3: same o, c+8,c+9                                              (b1, nt=2ntp+1)
__device__ uint32_t g_Bh[128 * 20480];
__device__ float g_stats[512];        // [(part*128+o)*2 + {sum,sq}]
__device__ float g_bnp[512];          // [(part*128+o)*2 + {scale,shift}]

__device__ __forceinline__ uint32_t pack_h2(float lo, float hi) {
    uint32_t r;
    asm("cvt.rn.f16x2.f32 %0, %1, %2;" : "=r"(r) : "f"(hi), "f"(lo));
    return r;
}
__device__ __forceinline__ void mma_f16(float* d, const uint32_t* a,
                                        const uint32_t* b) {
    asm volatile(
        "mma.sync.aligned.m16n8k16.row.col.f32.f16.f16.f32 "
        "{%0,%1,%2,%3}, {%4,%5,%6,%7}, {%8,%9}, {%0,%1,%2,%3};"
        : "+f"(d[0]), "+f"(d[1]), "+f"(d[2]), "+f"(d[3])
        : "r"(a[0]), "r"(a[1]), "r"(a[2]), "r"(a[3]), "r"(b[0]), "r"(b[1]));
}

// ---------------------------------------------------------------------------
__global__ void zero_stats_kernel() {
    if (threadIdx.x < 512) g_stats[threadIdx.x] = 0.f;
}

// B_j[o][c], j in {P0, P1, -Q1, P2, -Q2}, packed fp16 fragment layout (above).
__global__ void precompute_Bh_kernel(const float* __restrict__ filters) {
    __shared__ float ct[128], st[128];
    int h = blockIdx.x, t = threadIdx.x;
    if (t < 128) {
        float s_, c_;
        sincosf(TWO_PI * (float)t * (1.f / 128.f), &s_, &c_);
        ct[t] = c_; st[t] = s_;
    }
    __syncthreads();
    for (int e = t; e < 20480; e += blockDim.x) {
        int q   = e & 3;
        int tg  = (e >> 2) & 3;
        int gid = (e >> 4) & 7;
        int ntp = (e >> 7) & 7;
        int kt  = (e >> 10) & 3;
        int j   = e >> 12;
        int nt  = 2 * ntp + (q >> 1);
        int o   = nt * 8 + gid;
        int c   = kt * 16 + 2 * tg + (q & 1) * 8;
        int v = (j + 1) >> 1;                       // {0,1,1,2,2}
        bool sn = (j > 0) && ((j & 1) == 0);        // j==2 || j==4 -> -Q
        float b0 = 0.f, b1 = 0.f;
        #pragma unroll
        for (int u = 0; u < 3; u++) {
            int a = (h * u) & 127;
            float tr = sn ? st[a] : ct[a];
            b0 = fmaf(tr, filters[(u * 3 + v) * 8192 + c * 128 + o], b0);
            b1 = fmaf(tr, filters[(u * 3 + v) * 8192 + (c + 1) * 128 + o], b1);
        }
        if (sn) { b0 = -b0; b1 = -b1; }
        g_Bh[h * 20480 + e] = pack_h2(b0, b1);
    }
}

// ---------------------------------------------------------------------------
// Conv: 128 CTAs (one per h), 256 threads (8 warps), no main-loop barriers.
// Warp = one w per iteration (16 iterations). Per (j,kt16) step: 8 batched
// conflict-free lds.128 (fp16 B fragment pairs), then 16 m16n8k16 mma.
// A fragments from gmem, w-coefficients folded into A before fp16 pack.
#define SMEM_CONV (81920 + 2048)

__global__ __launch_bounds__(256, 1) void conv_mma_kernel(
    const float* __restrict__ xr, const float* __restrict__ xi,
    float* __restrict__ out)
{
    extern __shared__ float smem[];
    uint32_t* Bs = (uint32_t*)smem;       // 20480 uint32 = 80KB
    float* red = smem + 20480;            // 512 floats

    const int h = blockIdx.x, t = threadIdx.x;
    const int lane = t & 31, wid = t >> 5;
    const int gid = lane >> 2, tg = lane & 3;
    const int n0 = gid >> 1, part = gid & 1;

    // load resident B (coalesced uint4)
    {
        const uint4* src = (const uint4*)(g_Bh + h * 20480);
        uint4* dst = (uint4*)Bs;
        for (int g = t; g < 5120; g += 256) dst[g] = src[g];
    }
    for (int i = t; i < 512; i += 256) red[i] = 0.f;
    __syncthreads();

    // persistent BN stat registers: per nt, o-pair (2tg, 2tg+1)
    float ss0[16], qq0[16], ss1[16], qq1[16];
    #pragma unroll
    for (int i = 0; i < 16; i++) { ss0[i] = 0.f; qq0[i] = 0.f; ss1[i] = 0.f; qq1[i] = 0.f; }

    const float* xr0 = xr + ((size_t)(n0 * 128 + h) * 128) * 64;
    const float* xi0 = xi + ((size_t)(n0 * 128 + h) * 128) * 64;
    const float* xr4 = xr + ((size_t)((n0 + 4) * 128 + h) * 128) * 64;
    const float* xi4 = xi + ((size_t)((n0 + 4) * 128 + h) * 128) * 64;

    const uint4* B4 = (const uint4*)Bs;

    for (int it = 0; it < 16; it++) {
        const int w = it * 8 + wid;
        const float* pr0 = xr0 + w * 64;
        const float* pi0 = xi0 + w * 64;
        const float* pr4 = xr4 + w * 64;
        const float* pi4 = xi4 + w * 64;

        // raw A values (S or D by part), layout per kt16:
        // [kt*8 + {0:r0c0,1:r0c0+1,2:r0c8,3:r0c8+1,4:r1c0,5:r1c0+1,6:r1c8,7:r1c8+1}]
        float rawA[32];
        #pragma unroll
        for (int kt = 0; kt < 4; kt++) {
            int c0 = kt * 16 + 2 * tg;
            float2 r0a = *(const float2*)(pr0 + c0);
            float2 i0a = *(const float2*)(pi0 + c0);
            float2 r0b = *(const float2*)(pr0 + c0 + 8);
            float2 i0b = *(const float2*)(pi0 + c0 + 8);
            float2 r4a = *(const float2*)(pr4 + c0);
            float2 i4a = *(const float2*)(pi4 + c0);
            float2 r4b = *(const float2*)(pr4 + c0 + 8);
            float2 i4b = *(const float2*)(pi4 + c0 + 8);
            rawA[kt * 8 + 0] = part ? (i0a.x - r0a.x) : (r0a.x + i0a.x);
            rawA[kt * 8 + 1] = part ? (i0a.y - r0a.y) : (r0a.y + i0a.y);
            rawA[kt * 8 + 2] = part ? (i0b.x - r0b.x) : (r0b.x + i0b.x);
            rawA[kt * 8 + 3] = part ? (i0b.y - r0b.y) : (r0b.y + i0b.y);
            rawA[kt * 8 + 4] = part ? (i4a.x - r4a.x) : (r4a.x + i4a.x);
            rawA[kt * 8 + 5] = part ? (i4a.y - r4a.y) : (r4a.y + i4a.y);
            rawA[kt * 8 + 6] = part ? (i4b.x - r4b.x) : (r4b.x + i4b.x);
            rawA[kt * 8 + 7] = part ? (i4b.y - r4b.y) : (r4b.y + i4b.y);
        }

        float s1, c1f, s2, c2f;
        sincosf(TWO_PI * (float)w * (1.f / 128.f), &s1, &c1f);
        sincosf(TWO_PI * (float)((2 * w) & 127) * (1.f / 128.f), &s2, &c2f);

        float acc[16][4];
        #pragma unroll
        for (int nt = 0; nt < 16; nt++) {
            acc[nt][0] = 0.f; acc[nt][1] = 0.f; acc[nt][2] = 0.f; acc[nt][3] = 0.f;
        }

        #pragma unroll
        for (int s = 0; s < 20; s++) {
            const int j = s >> 2, kt = s & 3;
            const float cf = (j == 0) ? 1.f
                            : (j == 1) ? c1f
                            : (j == 2) ? s1
                            : (j == 3) ? c2f : s2;
            // batched conflict-free lds.128: 8 fragment-pair quads
            uint4 cur[8];
            #pragma unroll
            for (int p = 0; p < 8; p++)
                cur[p] = B4[s * 256 + p * 32 + lane];
            uint32_t a[4];
            a[0] = pack_h2(cf * rawA[kt * 8 + 0], cf * rawA[kt * 8 + 1]);
            a[1] = pack_h2(cf * rawA[kt * 8 + 4], cf * rawA[kt * 8 + 5]);
            a[2] = pack_h2(cf * rawA[kt * 8 + 2], cf * rawA[kt * 8 + 3]);
            a[3] = pack_h2(cf * rawA[kt * 8 + 6], cf * rawA[kt * 8 + 7]);
            #pragma unroll
            for (int p = 0; p < 8; p++) {
                mma_f16(acc[2 * p],     a, &cur[p].x);
                mma_f16(acc[2 * p + 1], a, &cur[p].z);
            }
        }

        // epilogue: store raw conv outputs + accumulate BN stats
        size_t ob = (size_t)part * 16777216 +
                    (((size_t)(n0 * 128 + h)) * 128 + w) * 128;
        size_t ob4 = ob + (size_t)4 * 128 * 128 * 128;
        #pragma unroll
        for (int nt = 0; nt < 16; nt++) {
            int o = nt * 8 + 2 * tg;
            *(float2*)(out + ob + o)  = make_float2(acc[nt][0], acc[nt][1]);
            *(float2*)(out + ob4 + o) = make_float2(acc[nt][2], acc[nt][3]);
            ss0[nt] += acc[nt][0] + acc[nt][2];
            qq0[nt] = fmaf(acc[nt][0], acc[nt][0], qq0[nt]);
            qq0[nt] = fmaf(acc[nt][2], acc[nt][2], qq0[nt]);
            ss1[nt] += acc[nt][1] + acc[nt][3];
            qq1[nt] = fmaf(acc[nt][1], acc[nt][1], qq1[nt]);
            qq1[nt] = fmaf(acc[nt][3], acc[nt][3], qq1[nt]);
        }
    }

    // stats: shuffle-reduce over same-part lanes (lane^8, lane^16), then smem
    #pragma unroll
    for (int nt = 0; nt < 16; nt++) {
        ss0[nt] += __shfl_xor_sync(~0u, ss0[nt], 8);
        ss0[nt] += __shfl_xor_sync(~0u, ss0[nt], 16);
        qq0[nt] += __shfl_xor_sync(~0u, qq0[nt], 8);
        qq0[nt] += __shfl_xor_sync(~0u, qq0[nt], 16);
        ss1[nt] += __shfl_xor_sync(~0u, ss1[nt], 8);
        ss1[nt] += __shfl_xor_sync(~0u, ss1[nt], 16);
        qq1[nt] += __shfl_xor_sync(~0u, qq1[nt], 8);
        qq1[nt] += __shfl_xor_sync(~0u, qq1[nt], 16);
    }
    if (lane < 8) {   // gid in {0,1}: part = gid, tg = lane&3
        #pragma unroll
        for (int nt = 0; nt < 16; nt++) {
            int o = nt * 8 + 2 * tg;
            atomicAdd(&red[(part * 128 + o) * 2 + 0], ss0[nt]);
            atomicAdd(&red[(part * 128 + o) * 2 + 1], qq0[nt]);
            atomicAdd(&red[(part * 128 + o + 1) * 2 + 0], ss1[nt]);
            atomicAdd(&red[(part * 128 + o + 1) * 2 + 1], qq1[nt]);
        }
    }
    __syncthreads();
    for (int i = t; i < 512; i += 256) atomicAdd(&g_stats[i], red[i]);
}

// ---------------------------------------------------------------------------
__global__ void bn_finalize_kernel(const float* __restrict__ gr,
                                   const float* __restrict__ br,
                                   const float* __restrict__ gi,
                                   const float* __restrict__ bi) {
    int t = threadIdx.x, part = t >> 7, o = t & 127;
    float sum = g_stats[t * 2 + 0], ss = g_stats[t * 2 + 1];
    const float inv = 1.f / 131072.f;
    float mean = sum * inv;
    float var = fmaf(-mean, mean, ss * inv);
    float gamma = part ? gi[o] : gr[o];
    float beta = part ? bi[o] : br[o];
    float a = gamma * rsqrtf(var + 1e-3f);
    g_bnp[t * 2 + 0] = a;
    g_bnp[t * 2 + 1] = fmaf(-mean, a, beta);
}

__global__ void bn_apply_kernel(float* __restrict__ out) {
    __shared__ float bp[512];
    int t = threadIdx.x;
    bp[t] = g_bnp[t];
    bp[t + 256] = g_bnp[t + 256];
    __syncthreads();
    const int total4 = 33554432 / 4;
    float4* o4 = (float4*)out;
    for (int i = blockIdx.x * blockDim.x + t; i < total4;
         i += gridDim.x * blockDim.x) {
        float4 x = o4[i];
        int e0 = i << 2;
        const float* b = bp + (e0 >> 24) * 256 + (e0 & 127) * 2;
        float v;
        v = fmaf(b[0], x.x, b[1]); x.x = v >= 0.f ? v : 0.2f * v;
        v = fmaf(b[2], x.y, b[3]); x.y = v >= 0.f ? v : 0.2f * v;
        v = fmaf(b[4], x.z, b[5]); x.z = v >= 0.f ? v : 0.2f * v;
        v = fmaf(b[6], x.w, b[7]); x.w = v >= 0.f ? v : 0.2f * v;
        o4[i] = x;
    }
}

// ---------------------------------------------------------------------------
extern "C" void kernel_launch(void* const* d_in, const int* in_sizes, int n_in,
                              void* d_out, int out_size) {
    const float* xr = (const float*)d_in[0];
    const float* xi = (const float*)d_in[1];
    const float* f  = (const float*)d_in[2];
    const float* gr = (const float*)d_in[3];
    const float* br = (const float*)d_in[4];
    const float* gi = (const float*)d_in[5];
    const float* bi = (const float*)d_in[6];
    float* out = (float*)d_out;

    cudaFuncSetAttribute(conv_mma_kernel,
                         cudaFuncAttributeMaxDynamicSharedMemorySize, SMEM_CONV);

    zero_stats_kernel<<<1, 512>>>();
    precompute_Bh_kernel<<<128, 256>>>(f);
    conv_mma_kernel<<<128, 256, SMEM_CONV>>>(xr, xi, out);
    bn_finalize_kernel<<<1, 256>>>(gr, br, gi, bi);
    bn_apply_kernel<<<2048, 256>>>(out);
}